// round 3
// baseline (speedup 1.0000x reference)
#include <cuda_runtime.h>
#include <cstdint>

#define N_NODES 100000
#define N_EDGES 1600000
#define IN_CH   128
#define OUT_CH  64

// ---------------- scratch (no allocations allowed) ----------------
__device__ float g_deg[N_NODES];
__device__ float g_dinv[N_NODES];
__device__ float g_h[(size_t)N_NODES * OUT_CH];

// ---------------- kernels ----------------

// Zero deg + output accumulator (d_out doubles as the accumulator).
__global__ void k_init(float* __restrict__ out) {
    int i = blockIdx.x * blockDim.x + threadIdx.x;
    int total = N_NODES * OUT_CH;
    if (i < total) out[i] = 0.0f;
    if (i < N_NODES) g_deg[i] = 0.0f;
}

// deg[col] += w  (scalar float atomics, spread addresses)
__global__ void k_deg(const int* __restrict__ eidx,
                      const float* __restrict__ ew) {
    int e = blockIdx.x * blockDim.x + threadIdx.x;
    if (e < N_EDGES) {
        int col = eidx[N_EDGES + e];
        atomicAdd(&g_deg[col], ew[e]);
    }
}

__global__ void k_dinv() {
    int i = blockIdx.x * blockDim.x + threadIdx.x;
    if (i < N_NODES) {
        float d = g_deg[i];
        g_dinv[i] = (d > 0.0f) ? rsqrtf(d) : 0.0f;
    }
}

// h = x @ W  (fp32, shared-memory tiled, 16 nodes per 256-thread block)
#define GEMM_NODES 16
#define WT_STRIDE  132
__global__ __launch_bounds__(256) void k_gemm(const float* __restrict__ x,
                                              const float* __restrict__ W) {
    __shared__ float Wt[OUT_CH * WT_STRIDE];    // 33.8 KB
    __shared__ float xs[GEMM_NODES * IN_CH];    // 8 KB

    int tid  = threadIdx.x;
    int base = blockIdx.x * GEMM_NODES;

    // load W [128 x 64] -> Wt[c*132 + k]
    for (int i = tid; i < IN_CH * OUT_CH; i += 256) {
        int k = i / OUT_CH, c = i % OUT_CH;
        Wt[c * WT_STRIDE + k] = W[i];
    }
    // load 16 x-rows
    {
        const float4* xin = (const float4*)(x + (size_t)base * IN_CH);
        float4* xsh = (float4*)xs;
        #pragma unroll
        for (int i = tid; i < GEMM_NODES * IN_CH / 4; i += 256)
            xsh[i] = xin[i];
    }
    __syncthreads();

    int col = tid & 63;       // 0..63
    int g   = tid >> 6;       // 0..3 -> nodes g*4 .. g*4+3
    float acc0 = 0.f, acc1 = 0.f, acc2 = 0.f, acc3 = 0.f;

    const float4* wrow = (const float4*)&Wt[col * WT_STRIDE];
    const float4* x0 = (const float4*)&xs[(g * 4 + 0) * IN_CH];
    const float4* x1 = (const float4*)&xs[(g * 4 + 1) * IN_CH];
    const float4* x2 = (const float4*)&xs[(g * 4 + 2) * IN_CH];
    const float4* x3 = (const float4*)&xs[(g * 4 + 3) * IN_CH];

    #pragma unroll
    for (int k4 = 0; k4 < IN_CH / 4; k4++) {
        float4 wv = wrow[k4];
        float4 a = x0[k4];
        acc0 += wv.x * a.x + wv.y * a.y + wv.z * a.z + wv.w * a.w;
        float4 b = x1[k4];
        acc1 += wv.x * b.x + wv.y * b.y + wv.z * b.z + wv.w * b.w;
        float4 c = x2[k4];
        acc2 += wv.x * c.x + wv.y * c.y + wv.z * c.z + wv.w * c.w;
        float4 d = x3[k4];
        acc3 += wv.x * d.x + wv.y * d.y + wv.z * d.z + wv.w * d.w;
    }

    float* hb = g_h + (size_t)(base + g * 4) * OUT_CH + col;
    hb[0 * OUT_CH] = acc0;
    hb[1 * OUT_CH] = acc1;
    hb[2 * OUT_CH] = acc2;
    hb[3 * OUT_CH] = acc3;
}

// Scatter: 16 threads per edge, each handles one float4 chunk of the 64-ch row.
__global__ __launch_bounds__(256) void k_scatter(const int* __restrict__ eidx,
                                                 const float* __restrict__ ew,
                                                 float* __restrict__ out) {
    unsigned t = blockIdx.x * 256u + threadIdx.x;
    unsigned e = t >> 4;
    unsigned c4 = t & 15u;
    if (e >= N_EDGES) return;

    int row = eidx[e];
    int col = eidx[N_EDGES + e];
    float norm = g_dinv[row] * ew[e] * g_dinv[col];

    const float4* hp = (const float4*)(g_h + (size_t)row * OUT_CH);
    float4 v = hp[c4];
    v.x *= norm; v.y *= norm; v.z *= norm; v.w *= norm;

    float4* op = (float4*)(out + (size_t)col * OUT_CH) + c4;
    asm volatile("red.global.add.v4.f32 [%0], {%1, %2, %3, %4};"
                 :: "l"(op), "f"(v.x), "f"(v.y), "f"(v.z), "f"(v.w)
                 : "memory");
}

// out = sigmoid(out + b)
__global__ void k_epilogue(float* __restrict__ out, const float* __restrict__ b) {
    int i = blockIdx.x * blockDim.x + threadIdx.x;
    if (i < N_NODES * OUT_CH) {
        float v = out[i] + b[i & 63];
        out[i] = 1.0f / (1.0f + __expf(-v));
    }
}

// ---------------- launch ----------------
extern "C" void kernel_launch(void* const* d_in, const int* in_sizes, int n_in,
                              void* d_out, int out_size) {
    const float* x   = (const float*)d_in[0];
    const int*   ei  = (const int*)d_in[1];
    const float* ew  = (const float*)d_in[2];
    const float* W   = (const float*)d_in[3];
    const float* b   = (const float*)d_in[4];
    float*       out = (float*)d_out;

    (void)in_sizes; (void)n_in; (void)out_size;

    k_init<<<(N_NODES * OUT_CH + 255) / 256, 256>>>(out);
    k_deg<<<(N_EDGES + 255) / 256, 256>>>(ei, ew);
    k_dinv<<<(N_NODES + 255) / 256, 256>>>();
    k_gemm<<<N_NODES / GEMM_NODES, 256>>>(x, W);
    k_scatter<<<(N_EDGES * 16 + 255) / 256, 256>>>(ei, ew, out);
    k_epilogue<<<(N_NODES * OUT_CH + 255) / 256, 256>>>(out, b);
}

// round 4
// speedup vs baseline: 1.3210x; 1.3210x over previous
#include <cuda_runtime.h>
#include <cstdint>

#define N_NODES 100000
#define N_EDGES 1600000
#define IN_CH   128
#define OUT_CH  64

// ---------------- scratch (no allocations allowed) ----------------
__device__ float g_deg[N_NODES];
__device__ float g_dinv[N_NODES];
__device__ float g_h[(size_t)N_NODES * OUT_CH];

// ---------------- kernels ----------------

__global__ void k_init(float* __restrict__ out) {
    int i = blockIdx.x * blockDim.x + threadIdx.x;
    int total = N_NODES * OUT_CH;
    if (i < total) out[i] = 0.0f;
    if (i < N_NODES) g_deg[i] = 0.0f;
}

__global__ void k_deg(const int* __restrict__ eidx,
                      const float* __restrict__ ew) {
    int e = blockIdx.x * blockDim.x + threadIdx.x;
    if (e < N_EDGES) {
        int col = eidx[N_EDGES + e];
        atomicAdd(&g_deg[col], ew[e]);
    }
}

__global__ void k_dinv() {
    int i = blockIdx.x * blockDim.x + threadIdx.x;
    if (i < N_NODES) {
        float d = g_deg[i];
        g_dinv[i] = (d > 0.0f) ? rsqrtf(d) : 0.0f;
    }
}

// h = x @ W, 2D register-blocked: block = 64 nodes x 64 cols, 256 threads,
// each thread computes a 4x4 tile. 2 B shared traffic per FFMA -> FMA-bound.
#define TN 64
__global__ __launch_bounds__(256) void k_gemm(const float* __restrict__ x,
                                              const float* __restrict__ W) {
    extern __shared__ float sm[];
    float* Ws = sm;                 // [128][64], native layout, 32 KB
    float* xs = sm + IN_CH * OUT_CH; // [64][128], 32 KB

    int tid  = threadIdx.x;
    int base = blockIdx.x * TN;

    // load W (8192 floats = 2048 float4)
    {
        float4* wv = (float4*)Ws;
        const float4* wi = (const float4*)W;
        #pragma unroll
        for (int i = tid; i < IN_CH * OUT_CH / 4; i += 256)
            wv[i] = wi[i];
    }
    // load 64 x-rows (guard last block)
    {
        float4* xv = (float4*)xs;
        const float4* xi = (const float4*)x;
        #pragma unroll
        for (int i = tid; i < TN * IN_CH / 4; i += 256) {
            int node = base + (i >> 5);                  // 32 float4 per node
            xv[i] = (node < N_NODES) ? xi[(size_t)node * (IN_CH / 4) + (i & 31)]
                                     : make_float4(0.f, 0.f, 0.f, 0.f);
        }
    }
    __syncthreads();

    int tx = tid & 15;        // col group: cols 4*tx .. 4*tx+3
    int ty = tid >> 4;        // node group: nodes 4*ty .. 4*ty+3
    int n0 = ty * 4;

    float acc[4][4] = {};
    const float4* wp = (const float4*)Ws + tx;   // + k*16 per k row

    #pragma unroll 4
    for (int k4 = 0; k4 < IN_CH / 4; k4++) {
        float4 xr0 = *(const float4*)&xs[(n0 + 0) * IN_CH + k4 * 4];
        float4 xr1 = *(const float4*)&xs[(n0 + 1) * IN_CH + k4 * 4];
        float4 xr2 = *(const float4*)&xs[(n0 + 2) * IN_CH + k4 * 4];
        float4 xr3 = *(const float4*)&xs[(n0 + 3) * IN_CH + k4 * 4];
        float4 wr0 = wp[(k4 * 4 + 0) * 16];
        float4 wr1 = wp[(k4 * 4 + 1) * 16];
        float4 wr2 = wp[(k4 * 4 + 2) * 16];
        float4 wr3 = wp[(k4 * 4 + 3) * 16];

        #pragma unroll
        for (int i = 0; i < 4; i++) {
            float4 a = (i == 0) ? xr0 : (i == 1) ? xr1 : (i == 2) ? xr2 : xr3;
            acc[i][0] += a.x * wr0.x + a.y * wr1.x + a.z * wr2.x + a.w * wr3.x;
            acc[i][1] += a.x * wr0.y + a.y * wr1.y + a.z * wr2.y + a.w * wr3.y;
            acc[i][2] += a.x * wr0.z + a.y * wr1.z + a.z * wr2.z + a.w * wr3.z;
            acc[i][3] += a.x * wr0.w + a.y * wr1.w + a.z * wr2.w + a.w * wr3.w;
        }
    }

    #pragma unroll
    for (int i = 0; i < 4; i++) {
        int node = base + n0 + i;
        if (node < N_NODES) {
            float4 v = make_float4(acc[i][0], acc[i][1], acc[i][2], acc[i][3]);
            *(float4*)&g_h[(size_t)node * OUT_CH + tx * 4] = v;
        }
    }
}

// Scatter: 16 threads per edge, each handles one float4 chunk of the 64-ch row.
__global__ __launch_bounds__(256) void k_scatter(const int* __restrict__ eidx,
                                                 const float* __restrict__ ew,
                                                 float* __restrict__ out) {
    unsigned t = blockIdx.x * 256u + threadIdx.x;
    unsigned e = t >> 4;
    unsigned c4 = t & 15u;
    if (e >= N_EDGES) return;

    int row = eidx[e];
    int col = eidx[N_EDGES + e];
    float norm = g_dinv[row] * ew[e] * g_dinv[col];

    const float4* hp = (const float4*)(g_h + (size_t)row * OUT_CH);
    float4 v = hp[c4];
    v.x *= norm; v.y *= norm; v.z *= norm; v.w *= norm;

    float4* op = (float4*)(out + (size_t)col * OUT_CH) + c4;
    asm volatile("red.global.add.v4.f32 [%0], {%1, %2, %3, %4};"
                 :: "l"(op), "f"(v.x), "f"(v.y), "f"(v.z), "f"(v.w)
                 : "memory");
}

// out = sigmoid(out + b), vectorized
__global__ void k_epilogue(float* __restrict__ out, const float* __restrict__ b) {
    int i = blockIdx.x * blockDim.x + threadIdx.x;   // float4 index
    if (i < N_NODES * OUT_CH / 4) {
        float4 v = ((float4*)out)[i];
        const float4 bb = ((const float4*)b)[i & 15];
        v.x = 1.0f / (1.0f + __expf(-(v.x + bb.x)));
        v.y = 1.0f / (1.0f + __expf(-(v.y + bb.y)));
        v.z = 1.0f / (1.0f + __expf(-(v.z + bb.z)));
        v.w = 1.0f / (1.0f + __expf(-(v.w + bb.w)));
        ((float4*)out)[i] = v;
    }
}

// ---------------- launch ----------------
extern "C" void kernel_launch(void* const* d_in, const int* in_sizes, int n_in,
                              void* d_out, int out_size) {
    const float* x   = (const float*)d_in[0];
    const int*   ei  = (const int*)d_in[1];
    const float* ew  = (const float*)d_in[2];
    const float* W   = (const float*)d_in[3];
    const float* b   = (const float*)d_in[4];
    float*       out = (float*)d_out;

    (void)in_sizes; (void)n_in; (void)out_size;

    int gemm_smem = (IN_CH * OUT_CH + TN * IN_CH) * (int)sizeof(float); // 64 KB
    cudaFuncSetAttribute(k_gemm, cudaFuncAttributeMaxDynamicSharedMemorySize, gemm_smem);

    k_init<<<(N_NODES * OUT_CH + 255) / 256, 256>>>(out);
    k_deg<<<(N_EDGES + 255) / 256, 256>>>(ei, ew);
    k_dinv<<<(N_NODES + 255) / 256, 256>>>();
    k_gemm<<<(N_NODES + TN - 1) / TN, 256, gemm_smem>>>(x, W);
    k_scatter<<<(N_EDGES * 16 + 255) / 256, 256>>>(ei, ew, out);
    k_epilogue<<<(N_NODES * OUT_CH / 4 + 255) / 256, 256>>>(out, b);
}